// round 5
// baseline (speedup 1.0000x reference)
#include <cuda_runtime.h>
#include <cuda_bf16.h>
#include <math.h>

// Problem constants (fixed by setup_inputs)
constexpr int B  = 4;
constexpr int H  = 256;
constexpr int W  = 256;
constexpr int C  = 256;
constexpr int K  = 1024;
constexpr int NP = 25;   // 5x5 window

// Mathematical reduction of the reference:
//   Each attention layer returns v_in + msg broadcast over the window axis n.
//   Every consumer of that tensor is a dot product followed by a softmax over
//   n, and softmax is shift-invariant -> both attention layers and all four
//   weight matrices cancel exactly.
//   Output = pos + softmax_n(s . X0[n]) . offsets, where X0 is the
//   channel-scrambled window gather (the reference's reshape quirk:
//   g = ch*25 + i*5 + j) and s = window-center feature vector
//   (s[ch] = win[ch*25 + 12]).
__global__ __launch_bounds__(256, 8)
void fine_match_kernel(const float* __restrict__ T,
                       const float* __restrict__ pos,
                       float* __restrict__ out) {
    __shared__ float win[NP * C];        // 25.6 KB
    __shared__ float corr_sm[NP];

    const int bk = blockIdx.x;           // 0 .. B*K-1
    const int b  = bk >> 10;             // K = 1024
    const int t  = threadIdx.x;          // 0..255 = channel index in gather

    const float pr = pos[bk * 2 + 0];
    const float pc = pos[bk * 2 + 1];
    const int r = (int)pr;               // astype(int32) truncation; positions >= 0
    const int c = (int)pc;

    const float* __restrict__ Tb = T + (size_t)b * H * W * C + t;

    // Gather the 25 window rows. Each thread loads channel t of each row
    // (fully coalesced 1024 B per row). All 25 loads are independent ->
    // front-batched LDGs, high MLP. Borders zero-padded.
    float v[NP];
    #pragma unroll
    for (int p = 0; p < NP; ++p) {
        const int i  = p / 5, j = p % 5;
        const int rr = r - 2 + i;
        const int cc = c - 2 + j;
        const bool ok = (rr >= 0) & (rr < H) & (cc >= 0) & (cc < W);
        v[p] = ok ? Tb[((size_t)rr * W + cc) * C] : 0.0f;
    }
    // Stride-25 word writes: gcd(25,32)=1 -> conflict-free.
    #pragma unroll
    for (int p = 0; p < NP; ++p)
        win[t * NP + p] = v[p];
    __syncthreads();

    // corr[n] = sum_ch s[ch] * win[n*256 + ch], with s[ch] = win[ch*25 + 12]
    const int warp = t >> 5;
    const int lane = t & 31;
    for (int n = warp; n < NP; n += 8) {
        float acc = 0.0f;
        #pragma unroll
        for (int ch = lane; ch < C; ch += 32)
            acc = fmaf(win[ch * NP + 12], win[n * C + ch], acc);
        #pragma unroll
        for (int o = 16; o; o >>= 1)
            acc += __shfl_xor_sync(0xffffffffu, acc, o);
        if (lane == 0) corr_sm[n] = acc;
    }
    __syncthreads();

    // Softmax over 25 logits + expectation over offsets (warp 0 only).
    if (warp == 0) {
        const bool valid = (lane < NP);
        float lv = valid ? corr_sm[lane] : -INFINITY;
        float m = lv;
        #pragma unroll
        for (int o = 16; o; o >>= 1)
            m = fmaxf(m, __shfl_xor_sync(0xffffffffu, m, o));
        float e = valid ? expf(lv - m) : 0.0f;
        float sum = e;
        #pragma unroll
        for (int o = 16; o; o >>= 1)
            sum += __shfl_xor_sync(0xffffffffu, sum, o);

        // off1d = linspace(-3, 2, 5) = -3 + 1.25*idx (faithful to -w//2 = -3)
        float ox = 0.0f, oy = 0.0f;
        if (valid) {
            ox = -3.0f + 1.25f * (float)(lane / 5);
            oy = -3.0f + 1.25f * (float)(lane % 5);
        }
        float dx = e * ox;
        float dy = e * oy;
        #pragma unroll
        for (int o = 16; o; o >>= 1) {
            dx += __shfl_xor_sync(0xffffffffu, dx, o);
            dy += __shfl_xor_sync(0xffffffffu, dy, o);
        }
        if (lane == 0) {
            const float inv = 1.0f / sum;
            out[bk * 2 + 0] = pr + dx * inv;
            out[bk * 2 + 1] = pc + dy * inv;
        }
    }
}

extern "C" void kernel_launch(void* const* d_in, const int* in_sizes, int n_in,
                              void* d_out, int out_size) {
    // metadata order: source_features, target_features, coarse_positions,
    //                 Wq, Wk, Wv, Wo.
    // source_features and all weight matrices are provably unused (softmax
    // shift-invariance eliminates the attention layers entirely).
    const float* target = (const float*)d_in[1];
    const float* pos    = (const float*)d_in[2];
    float* out          = (float*)d_out;

    const int n_points = in_sizes[2] / 2;   // B*K = 4096 for the pinned shape
    fine_match_kernel<<<n_points, 256>>>(target, pos, out);
}